// round 15
// baseline (speedup 1.0000x reference)
#include <cuda_runtime.h>

#define MAX_N 100000
#define MAX_E 1200000
#define MAX_EP (MAX_E + 3 * MAX_N)   // padded bins: each row rounded up to 4
#define FDIM 64

__device__ float g_Q[(size_t)MAX_N * FDIM];      // Q = X@W1 + (X*X)@W2
__device__ int   g_cnt[MAX_N];                   // per-row edge count
__device__ int   g_rowstart[MAX_N];              // exclusive scan of padded counts
__device__ int   g_cursor[MAX_N];                // scatter cursor
__device__ int2  g_edges[MAX_EP];                // binned (col, val), zero-padded to x4
__device__ int   g_bsum[128];                    // block sums for the scan

// ---- packed f32x2 helpers (sm_103a FFMA2: 2 fp32 FMAs / issue slot) ----
typedef unsigned long long u64;
__device__ __forceinline__ u64 pack2(float lo, float hi) {
    u64 r; asm("mov.b64 %0, {%1, %2};" : "=l"(r) : "f"(lo), "f"(hi)); return r;
}
__device__ __forceinline__ void unpack2(u64 p, float& lo, float& hi) {
    asm("mov.b64 {%0, %1}, %2;" : "=f"(lo), "=f"(hi) : "l"(p));
}
__device__ __forceinline__ u64 fma2(u64 a, u64 b, u64 c) {
    u64 d; asm("fma.rn.f32x2 %0, %1, %2, %3;" : "=l"(d) : "l"(a), "l"(b), "l"(c)); return d;
}
__device__ __forceinline__ u64 mul2(u64 a, u64 b) {
    u64 d; asm("mul.rn.f32x2 %0, %1, %2;" : "=l"(d) : "l"(a), "l"(b)); return d;
}

// ---------------------------------------------------------------------------
// Dense GEMM (f32x2) + fused histogram. 64-row tile, 4 rows/thread, 48KB,
// 3 blocks/SM. NEW: k chunked by 4 — X read as one LDS.128 per row per
// 4 k's (X wavefronts 4x down), W pairs read as LDS.128 (fewer issues).
// ---------------------------------------------------------------------------
__global__ __launch_bounds__(256, 3) void gnn_dense_hist(
    const float* __restrict__ X,
    const float* __restrict__ W1, const float* __restrict__ b1,
    const float* __restrict__ W2, const float* __restrict__ b2,
    const int* __restrict__ rows,
    float* __restrict__ out, int N, int E)
{
    extern __shared__ float smem[];
    float* W1s = smem;          // 64*64 = 16KB
    float* W2s = smem + 4096;   // 16KB
    float* Xs  = smem + 8192;   // 64*64 = 16KB

    const int tid = threadIdx.x;

    #pragma unroll
    for (int i = tid; i < 1024; i += 256) {
        reinterpret_cast<float4*>(W1s)[i] = reinterpret_cast<const float4*>(W1)[i];
        reinterpret_cast<float4*>(W2s)[i] = reinterpret_cast<const float4*>(W2)[i];
    }

    const int row0 = blockIdx.x * 64;
    #pragma unroll
    for (int i = tid; i < 64 * 16; i += 256) {
        const int r  = i >> 4;
        const int gr = row0 + r;
        float4 v = make_float4(0.f, 0.f, 0.f, 0.f);
        if (gr < N) v = reinterpret_cast<const float4*>(X)[(size_t)gr * 16 + (i & 15)];
        reinterpret_cast<float4*>(Xs)[i] = v;
    }

    const int stride = gridDim.x * 256;
    for (int e = blockIdx.x * 256 + tid; e < E; e += stride)
        atomicAdd(&g_cnt[__ldg(rows + e)], 1);

    __syncthreads();

    const int rg  = (tid >> 4) * 4;
    const int cg4 = tid & 15;

    const float4* Xs4 = reinterpret_cast<const float4*>(Xs);
    // W pairs (2 contiguous u64 = 1 float4) per k at u64 index k*32 + 2*cg4
    const ulonglong2* W1q = reinterpret_cast<const ulonglong2*>(W1s);
    const ulonglong2* W2q = reinterpret_cast<const ulonglong2*>(W2s);

    u64 acc1a[4], acc1b[4], acc2a[4], acc2b[4];
    #pragma unroll
    for (int i = 0; i < 4; ++i) { acc1a[i]=0; acc1b[i]=0; acc2a[i]=0; acc2b[i]=0; }

    #pragma unroll 4
    for (int kk = 0; kk < 16; ++kk) {
        float4 xv[4];
        #pragma unroll
        for (int i = 0; i < 4; ++i) xv[i] = Xs4[(rg + i) * 16 + kk];

        #pragma unroll
        for (int kq = 0; kq < 4; ++kq) {
            const int k = kk * 4 + kq;
            const ulonglong2 w1 = W1q[k * 16 + cg4];   // {w1a, w1b} LDS.128
            const ulonglong2 w2 = W2q[k * 16 + cg4];   // {w2a, w2b} LDS.128
            #pragma unroll
            for (int i = 0; i < 4; ++i) {
                const float x = (kq == 0) ? xv[i].x :
                                (kq == 1) ? xv[i].y :
                                (kq == 2) ? xv[i].z : xv[i].w;
                const u64 xp  = pack2(x, x);
                const u64 xsq = mul2(xp, xp);
                acc1a[i] = fma2(xp,  w1.x, acc1a[i]);
                acc1b[i] = fma2(xp,  w1.y, acc1b[i]);
                acc2a[i] = fma2(xsq, w2.x, acc2a[i]);
                acc2b[i] = fma2(xsq, w2.y, acc2b[i]);
            }
        }
    }

    const int cc = cg4 * 4;
    float4 bb;
    bb.x = __ldg(b1 + cc + 0) + __ldg(b2 + cc + 0);
    bb.y = __ldg(b1 + cc + 1) + __ldg(b2 + cc + 1);
    bb.z = __ldg(b1 + cc + 2) + __ldg(b2 + cc + 2);
    bb.w = __ldg(b1 + cc + 3) + __ldg(b2 + cc + 3);

    #pragma unroll
    for (int i = 0; i < 4; ++i) {
        const int gr = row0 + rg + i;
        if (gr < N) {
            float a10, a11, a12, a13, a20, a21, a22, a23;
            unpack2(acc1a[i], a10, a11);
            unpack2(acc1b[i], a12, a13);
            unpack2(acc2a[i], a20, a21);
            unpack2(acc2b[i], a22, a23);
            float4 o, q;
            o.x = a10 + bb.x;  q.x = a10 + a20;
            o.y = a11 + bb.y;  q.y = a11 + a21;
            o.z = a12 + bb.z;  q.z = a12 + a22;
            o.w = a13 + bb.w;  q.w = a13 + a23;
            reinterpret_cast<float4*>(out)[(size_t)gr * 16 + cg4] = o;
            reinterpret_cast<float4*>(g_Q)[(size_t)gr * 16 + cg4] = q;
        }
    }
}

// ---------------------------------------------------------------------------
// Scan stage (R12 structure, byte-identical): padded counts vp = (cnt+3)&~3.
// ---------------------------------------------------------------------------
__device__ __forceinline__ int warp_incl_scan(int v) {
    #pragma unroll
    for (int off = 1; off < 32; off <<= 1) {
        int u = __shfl_up_sync(0xffffffffu, v, off);
        if ((threadIdx.x & 31) >= off) v += u;
    }
    return v;
}

__global__ __launch_bounds__(1024) void scan_blocksums(int N) {
    const int i = blockIdx.x * 1024 + threadIdx.x;
    int v = (i < N) ? ((g_cnt[i] + 3) & ~3) : 0;
    #pragma unroll
    for (int off = 16; off > 0; off >>= 1)
        v += __shfl_down_sync(0xffffffffu, v, off);
    __shared__ int ws[32];
    const int lane = threadIdx.x & 31, wid = threadIdx.x >> 5;
    if (lane == 0) ws[wid] = v;
    __syncthreads();
    if (wid == 0) {
        int x = ws[lane];
        #pragma unroll
        for (int off = 16; off > 0; off >>= 1)
            x += __shfl_down_sync(0xffffffffu, x, off);
        if (lane == 0) g_bsum[blockIdx.x] = x;
    }
}

__global__ __launch_bounds__(128) void scan_bsums(int nb) {
    __shared__ int s[128];
    const int t = threadIdx.x;
    s[t] = (t < nb) ? g_bsum[t] : 0;
    __syncthreads();
    #pragma unroll
    for (int off = 1; off < 128; off <<= 1) {
        int v = (t >= off) ? s[t - off] : 0;
        __syncthreads();
        s[t] += v;
        __syncthreads();
    }
    if (t < nb) g_bsum[t] = s[t];
}

__global__ __launch_bounds__(1024) void scan_write(int N) {
    const int t = threadIdx.x, b = blockIdx.x;
    const int i = b * 1024 + t;
    const int cnt = (i < N) ? g_cnt[i] : 0;
    const int vp  = (cnt + 3) & ~3;
    const int lane = t & 31, wid = t >> 5;
    int inc = warp_incl_scan(vp);
    __shared__ int ws[32];
    if (lane == 31) ws[wid] = inc;
    __syncthreads();
    if (wid == 0) {
        int x = ws[lane];
        x = warp_incl_scan(x);
        ws[lane] = x;
    }
    __syncthreads();
    int excl = inc - vp + (wid ? ws[wid - 1] : 0) + (b ? g_bsum[b - 1] : 0);
    if (i < N) {
        g_rowstart[i] = excl;
        g_cursor[i]   = excl;
        const int2 z = make_int2(0, 0);
        for (int p = excl + cnt; p < excl + vp; ++p) g_edges[p] = z;
    }
}

__global__ __launch_bounds__(256) void gnn_scatter(
    const int* __restrict__ rows,
    const int* __restrict__ cols,
    const float* __restrict__ vals, int E)
{
    const int e = blockIdx.x * blockDim.x + threadIdx.x;
    if (e >= E) return;
    const int r   = __ldg(rows + e);
    const int pos = atomicAdd(&g_cursor[r], 1);
    g_edges[pos] = make_int2(__ldg(cols + e), __float_as_int(__ldg(vals + e)));
}

// ---------------------------------------------------------------------------
// CSR SpMM: 16 lanes/row, float4/lane, padded bins, edge prefetch.
// (R12 measured-best, byte-identical)
// ---------------------------------------------------------------------------
__global__ __launch_bounds__(256) void gnn_spmm_csr(float* __restrict__ out, int N)
{
    const int gid = blockIdx.x * blockDim.x + threadIdx.x;
    const int row = gid >> 4;
    if (row >= N) return;
    const int lane16 = gid & 15;

    const int start = __ldg(g_rowstart + row);
    const int end   = __ldg(g_cursor + row);      // = start + cnt
    const int deg   = end - start;
    if (deg <= 0) return;
    int iters = (deg + 3) >> 2;

    const float4* __restrict__ Q4 = reinterpret_cast<const float4*>(g_Q);
    const int2* ep = g_edges + start;

    int2 c0 = __ldg(ep + 0), c1 = __ldg(ep + 1);
    int2 c2 = __ldg(ep + 2), c3 = __ldg(ep + 3);

    float4 acc = make_float4(0.f, 0.f, 0.f, 0.f);

    while (--iters > 0) {
        ep += 4;
        const int2 n0 = __ldg(ep + 0), n1 = __ldg(ep + 1);
        const int2 n2 = __ldg(ep + 2), n3 = __ldg(ep + 3);

        const float4 q0 = __ldg(Q4 + (size_t)c0.x * 16 + lane16);
        const float4 q1 = __ldg(Q4 + (size_t)c1.x * 16 + lane16);
        const float4 q2 = __ldg(Q4 + (size_t)c2.x * 16 + lane16);
        const float4 q3 = __ldg(Q4 + (size_t)c3.x * 16 + lane16);
        const float v0 = __int_as_float(c0.y);
        const float v1 = __int_as_float(c1.y);
        const float v2 = __int_as_float(c2.y);
        const float v3 = __int_as_float(c3.y);
        acc.x = fmaf(v0, q0.x, acc.x); acc.y = fmaf(v0, q0.y, acc.y);
        acc.z = fmaf(v0, q0.z, acc.z); acc.w = fmaf(v0, q0.w, acc.w);
        acc.x = fmaf(v1, q1.x, acc.x); acc.y = fmaf(v1, q1.y, acc.y);
        acc.z = fmaf(v1, q1.z, acc.z); acc.w = fmaf(v1, q1.w, acc.w);
        acc.x = fmaf(v2, q2.x, acc.x); acc.y = fmaf(v2, q2.y, acc.y);
        acc.z = fmaf(v2, q2.z, acc.z); acc.w = fmaf(v2, q2.w, acc.w);
        acc.x = fmaf(v3, q3.x, acc.x); acc.y = fmaf(v3, q3.y, acc.y);
        acc.z = fmaf(v3, q3.z, acc.z); acc.w = fmaf(v3, q3.w, acc.w);

        c0 = n0; c1 = n1; c2 = n2; c3 = n3;
    }

    {   // final chunk (padding edges have val=0 -> no-op FMAs)
        const float4 q0 = __ldg(Q4 + (size_t)c0.x * 16 + lane16);
        const float4 q1 = __ldg(Q4 + (size_t)c1.x * 16 + lane16);
        const float4 q2 = __ldg(Q4 + (size_t)c2.x * 16 + lane16);
        const float4 q3 = __ldg(Q4 + (size_t)c3.x * 16 + lane16);
        const float v0 = __int_as_float(c0.y);
        const float v1 = __int_as_float(c1.y);
        const float v2 = __int_as_float(c2.y);
        const float v3 = __int_as_float(c3.y);
        acc.x = fmaf(v0, q0.x, acc.x); acc.y = fmaf(v0, q0.y, acc.y);
        acc.z = fmaf(v0, q0.z, acc.z); acc.w = fmaf(v0, q0.w, acc.w);
        acc.x = fmaf(v1, q1.x, acc.x); acc.y = fmaf(v1, q1.y, acc.y);
        acc.z = fmaf(v1, q1.z, acc.z); acc.w = fmaf(v1, q1.w, acc.w);
        acc.x = fmaf(v2, q2.x, acc.x); acc.y = fmaf(v2, q2.y, acc.y);
        acc.z = fmaf(v2, q2.z, acc.z); acc.w = fmaf(v2, q2.w, acc.w);
        acc.x = fmaf(v3, q3.x, acc.x); acc.y = fmaf(v3, q3.y, acc.y);
        acc.z = fmaf(v3, q3.z, acc.z); acc.w = fmaf(v3, q3.w, acc.w);
    }

    float4* orow = reinterpret_cast<float4*>(out) + (size_t)row * 16 + lane16;
    float4 o = *orow;
    o.x += acc.x; o.y += acc.y; o.z += acc.z; o.w += acc.w;
    *orow = o;
}

extern "C" void kernel_launch(void* const* d_in, const int* in_sizes, int n_in,
                              void* d_out, int out_size)
{
    const int*   rows = (const int*)  d_in[0];
    const int*   cols = (const int*)  d_in[1];
    const float* vals = (const float*)d_in[2];
    const float* X    = (const float*)d_in[3];
    const float* W1   = (const float*)d_in[4];
    const float* b1   = (const float*)d_in[5];
    const float* W2   = (const float*)d_in[6];
    const float* b2   = (const float*)d_in[7];
    float* out = (float*)d_out;

    const int E = in_sizes[0];
    const int N = in_sizes[3] / FDIM;

    cudaFuncSetAttribute(gnn_dense_hist, cudaFuncAttributeMaxDynamicSharedMemorySize, 49152);

    void* p = nullptr;
    cudaGetSymbolAddress(&p, g_cnt);
    cudaMemsetAsync(p, 0, (size_t)N * sizeof(int));

    const int blocksD = (N + 63) / 64;
    gnn_dense_hist<<<blocksD, 256, 49152>>>(X, W1, b1, W2, b2, rows, out, N, E);

    const int nb = (N + 1023) / 1024;
    scan_blocksums<<<nb, 1024>>>(N);
    scan_bsums<<<1, 128>>>(nb);
    scan_write<<<nb, 1024>>>(N);

    gnn_scatter<<<(E + 255) / 256, 256>>>(rows, cols, vals, E);

    const long long work = (long long)N * 16;
    gnn_spmm_csr<<<(int)((work + 255) / 256), 256>>>(out, N);
}

// round 16
// speedup vs baseline: 1.0171x; 1.0171x over previous
#include <cuda_runtime.h>

#define MAX_N 100000
#define MAX_E 1200000
#define MAX_EP (MAX_E + 3 * MAX_N)   // padded bins: each row rounded up to 4
#define FDIM 64

__device__ float g_Q[(size_t)MAX_N * FDIM];      // Q = X@W1 + (X*X)@W2
__device__ int   g_cnt[MAX_N];                   // per-row edge count
__device__ int   g_rank[MAX_E];                  // edge's rank within its row
__device__ int   g_rowstart[MAX_N];              // exclusive scan of padded counts
__device__ int   g_rowend[MAX_N];                // rowstart + cnt
__device__ int2  g_edges[MAX_EP];                // binned (col, val), zero-padded to x4
__device__ int   g_bsum[128];                    // block sums for the scan

// ---- packed f32x2 helpers (sm_103a FFMA2: 2 fp32 FMAs / issue slot) ----
typedef unsigned long long u64;
__device__ __forceinline__ u64 pack2(float lo, float hi) {
    u64 r; asm("mov.b64 %0, {%1, %2};" : "=l"(r) : "f"(lo), "f"(hi)); return r;
}
__device__ __forceinline__ void unpack2(u64 p, float& lo, float& hi) {
    asm("mov.b64 {%0, %1}, %2;" : "=f"(lo), "=f"(hi) : "l"(p));
}
__device__ __forceinline__ u64 fma2(u64 a, u64 b, u64 c) {
    u64 d; asm("fma.rn.f32x2 %0, %1, %2, %3;" : "=l"(d) : "l"(a), "l"(b), "l"(c)); return d;
}
__device__ __forceinline__ u64 mul2(u64 a, u64 b) {
    u64 d; asm("mul.rn.f32x2 %0, %1, %2;" : "=l"(d) : "l"(a), "l"(b)); return d;
}

// ---------------------------------------------------------------------------
// Dense GEMM (f32x2) + fused histogram that KEEPS the atomic's return value:
// g_rank[e] = old count = edge's rank within its row. The extra 4.8MB store
// hides under the FFMA-bound GEMM loop like the histogram always has.
// ---------------------------------------------------------------------------
__global__ __launch_bounds__(256, 3) void gnn_dense_hist(
    const float* __restrict__ X,
    const float* __restrict__ W1, const float* __restrict__ b1,
    const float* __restrict__ W2, const float* __restrict__ b2,
    const int* __restrict__ rows,
    float* __restrict__ out, int N, int E)
{
    extern __shared__ float smem[];
    float* W1s = smem;          // 64*64 = 16KB
    float* W2s = smem + 4096;   // 16KB
    float* Xs  = smem + 8192;   // 64*64 = 16KB

    const int tid = threadIdx.x;

    #pragma unroll
    for (int i = tid; i < 1024; i += 256) {
        reinterpret_cast<float4*>(W1s)[i] = reinterpret_cast<const float4*>(W1)[i];
        reinterpret_cast<float4*>(W2s)[i] = reinterpret_cast<const float4*>(W2)[i];
    }

    const int row0 = blockIdx.x * 64;
    #pragma unroll
    for (int i = tid; i < 64 * 16; i += 256) {
        const int r  = i >> 4;
        const int gr = row0 + r;
        float4 v = make_float4(0.f, 0.f, 0.f, 0.f);
        if (gr < N) v = reinterpret_cast<const float4*>(X)[(size_t)gr * 16 + (i & 15)];
        reinterpret_cast<float4*>(Xs)[i] = v;
    }

    // Fused histogram + rank capture.
    const int stride = gridDim.x * 256;
    for (int e = blockIdx.x * 256 + tid; e < E; e += stride)
        g_rank[e] = atomicAdd(&g_cnt[__ldg(rows + e)], 1);

    __syncthreads();

    const int rg  = (tid >> 4) * 4;
    const int cg4 = tid & 15;

    const u64* W1p = reinterpret_cast<const u64*>(W1s);
    const u64* W2p = reinterpret_cast<const u64*>(W2s);

    u64 acc1a[4], acc1b[4], acc2a[4], acc2b[4];
    #pragma unroll
    for (int i = 0; i < 4; ++i) { acc1a[i]=0; acc1b[i]=0; acc2a[i]=0; acc2b[i]=0; }

    #pragma unroll 8
    for (int k = 0; k < 64; ++k) {
        const u64 w1a = W1p[k * 32 + 2 * cg4];
        const u64 w1b = W1p[k * 32 + 2 * cg4 + 1];
        const u64 w2a = W2p[k * 32 + 2 * cg4];
        const u64 w2b = W2p[k * 32 + 2 * cg4 + 1];
        #pragma unroll
        for (int i = 0; i < 4; ++i) {
            const float x  = Xs[(rg + i) * 64 + k];
            const u64 xp  = pack2(x, x);
            const u64 xsq = mul2(xp, xp);
            acc1a[i] = fma2(xp,  w1a, acc1a[i]);
            acc1b[i] = fma2(xp,  w1b, acc1b[i]);
            acc2a[i] = fma2(xsq, w2a, acc2a[i]);
            acc2b[i] = fma2(xsq, w2b, acc2b[i]);
        }
    }

    const int cc = cg4 * 4;
    float4 bb;
    bb.x = __ldg(b1 + cc + 0) + __ldg(b2 + cc + 0);
    bb.y = __ldg(b1 + cc + 1) + __ldg(b2 + cc + 1);
    bb.z = __ldg(b1 + cc + 2) + __ldg(b2 + cc + 2);
    bb.w = __ldg(b1 + cc + 3) + __ldg(b2 + cc + 3);

    #pragma unroll
    for (int i = 0; i < 4; ++i) {
        const int gr = row0 + rg + i;
        if (gr < N) {
            float a10, a11, a12, a13, a20, a21, a22, a23;
            unpack2(acc1a[i], a10, a11);
            unpack2(acc1b[i], a12, a13);
            unpack2(acc2a[i], a20, a21);
            unpack2(acc2b[i], a22, a23);
            float4 o, q;
            o.x = a10 + bb.x;  q.x = a10 + a20;
            o.y = a11 + bb.y;  q.y = a11 + a21;
            o.z = a12 + bb.z;  q.z = a12 + a22;
            o.w = a13 + bb.w;  q.w = a13 + a23;
            reinterpret_cast<float4*>(out)[(size_t)gr * 16 + cg4] = o;
            reinterpret_cast<float4*>(g_Q)[(size_t)gr * 16 + cg4] = q;
        }
    }
}

// ---------------------------------------------------------------------------
// Scan stage (R12 structure): padded counts vp = (cnt+3)&~3.
// scan_write sets rowend = rowstart + cnt (no cursor needed anymore).
// ---------------------------------------------------------------------------
__device__ __forceinline__ int warp_incl_scan(int v) {
    #pragma unroll
    for (int off = 1; off < 32; off <<= 1) {
        int u = __shfl_up_sync(0xffffffffu, v, off);
        if ((threadIdx.x & 31) >= off) v += u;
    }
    return v;
}

__global__ __launch_bounds__(1024) void scan_blocksums(int N) {
    const int i = blockIdx.x * 1024 + threadIdx.x;
    int v = (i < N) ? ((g_cnt[i] + 3) & ~3) : 0;
    #pragma unroll
    for (int off = 16; off > 0; off >>= 1)
        v += __shfl_down_sync(0xffffffffu, v, off);
    __shared__ int ws[32];
    const int lane = threadIdx.x & 31, wid = threadIdx.x >> 5;
    if (lane == 0) ws[wid] = v;
    __syncthreads();
    if (wid == 0) {
        int x = ws[lane];
        #pragma unroll
        for (int off = 16; off > 0; off >>= 1)
            x += __shfl_down_sync(0xffffffffu, x, off);
        if (lane == 0) g_bsum[blockIdx.x] = x;
    }
}

__global__ __launch_bounds__(128) void scan_bsums(int nb) {
    __shared__ int s[128];
    const int t = threadIdx.x;
    s[t] = (t < nb) ? g_bsum[t] : 0;
    __syncthreads();
    #pragma unroll
    for (int off = 1; off < 128; off <<= 1) {
        int v = (t >= off) ? s[t - off] : 0;
        __syncthreads();
        s[t] += v;
        __syncthreads();
    }
    if (t < nb) g_bsum[t] = s[t];
}

__global__ __launch_bounds__(1024) void scan_write(int N) {
    const int t = threadIdx.x, b = blockIdx.x;
    const int i = b * 1024 + t;
    const int cnt = (i < N) ? g_cnt[i] : 0;
    const int vp  = (cnt + 3) & ~3;
    const int lane = t & 31, wid = t >> 5;
    int inc = warp_incl_scan(vp);
    __shared__ int ws[32];
    if (lane == 31) ws[wid] = inc;
    __syncthreads();
    if (wid == 0) {
        int x = ws[lane];
        x = warp_incl_scan(x);
        ws[lane] = x;
    }
    __syncthreads();
    int excl = inc - vp + (wid ? ws[wid - 1] : 0) + (b ? g_bsum[b - 1] : 0);
    if (i < N) {
        g_rowstart[i] = excl;
        g_rowend[i]   = excl + cnt;
        const int2 z = make_int2(0, 0);
        for (int p = excl + cnt; p < excl + vp; ++p) g_edges[p] = z;
    }
}

// ---------------------------------------------------------------------------
// Scatter: ATOMIC-FREE. Position = rowstart[r] + rank[e] (rank captured by
// the fused histogram). Pure loads + one scattered 8B store per edge.
// ---------------------------------------------------------------------------
__global__ __launch_bounds__(256) void gnn_scatter(
    const int* __restrict__ rows,
    const int* __restrict__ cols,
    const float* __restrict__ vals, int E)
{
    const int e = blockIdx.x * blockDim.x + threadIdx.x;
    if (e >= E) return;
    const int r   = __ldg(rows + e);
    const int pos = __ldg(g_rowstart + r) + __ldg(g_rank + e);
    g_edges[pos] = make_int2(__ldg(cols + e), __float_as_int(__ldg(vals + e)));
}

// ---------------------------------------------------------------------------
// CSR SpMM: 16 lanes/row, float4/lane, padded bins, edge prefetch.
// (R12 measured-best, byte-identical apart from rowend rename)
// ---------------------------------------------------------------------------
__global__ __launch_bounds__(256) void gnn_spmm_csr(float* __restrict__ out, int N)
{
    const int gid = blockIdx.x * blockDim.x + threadIdx.x;
    const int row = gid >> 4;
    if (row >= N) return;
    const int lane16 = gid & 15;

    const int start = __ldg(g_rowstart + row);
    const int end   = __ldg(g_rowend + row);
    const int deg   = end - start;
    if (deg <= 0) return;
    int iters = (deg + 3) >> 2;

    const float4* __restrict__ Q4 = reinterpret_cast<const float4*>(g_Q);
    const int2* ep = g_edges + start;

    int2 c0 = __ldg(ep + 0), c1 = __ldg(ep + 1);
    int2 c2 = __ldg(ep + 2), c3 = __ldg(ep + 3);

    float4 acc = make_float4(0.f, 0.f, 0.f, 0.f);

    while (--iters > 0) {
        ep += 4;
        const int2 n0 = __ldg(ep + 0), n1 = __ldg(ep + 1);
        const int2 n2 = __ldg(ep + 2), n3 = __ldg(ep + 3);

        const float4 q0 = __ldg(Q4 + (size_t)c0.x * 16 + lane16);
        const float4 q1 = __ldg(Q4 + (size_t)c1.x * 16 + lane16);
        const float4 q2 = __ldg(Q4 + (size_t)c2.x * 16 + lane16);
        const float4 q3 = __ldg(Q4 + (size_t)c3.x * 16 + lane16);
        const float v0 = __int_as_float(c0.y);
        const float v1 = __int_as_float(c1.y);
        const float v2 = __int_as_float(c2.y);
        const float v3 = __int_as_float(c3.y);
        acc.x = fmaf(v0, q0.x, acc.x); acc.y = fmaf(v0, q0.y, acc.y);
        acc.z = fmaf(v0, q0.z, acc.z); acc.w = fmaf(v0, q0.w, acc.w);
        acc.x = fmaf(v1, q1.x, acc.x); acc.y = fmaf(v1, q1.y, acc.y);
        acc.z = fmaf(v1, q1.z, acc.z); acc.w = fmaf(v1, q1.w, acc.w);
        acc.x = fmaf(v2, q2.x, acc.x); acc.y = fmaf(v2, q2.y, acc.y);
        acc.z = fmaf(v2, q2.z, acc.z); acc.w = fmaf(v2, q2.w, acc.w);
        acc.x = fmaf(v3, q3.x, acc.x); acc.y = fmaf(v3, q3.y, acc.y);
        acc.z = fmaf(v3, q3.z, acc.z); acc.w = fmaf(v3, q3.w, acc.w);

        c0 = n0; c1 = n1; c2 = n2; c3 = n3;
    }

    {   // final chunk (padding edges have val=0 -> no-op FMAs)
        const float4 q0 = __ldg(Q4 + (size_t)c0.x * 16 + lane16);
        const float4 q1 = __ldg(Q4 + (size_t)c1.x * 16 + lane16);
        const float4 q2 = __ldg(Q4 + (size_t)c2.x * 16 + lane16);
        const float4 q3 = __ldg(Q4 + (size_t)c3.x * 16 + lane16);
        const float v0 = __int_as_float(c0.y);
        const float v1 = __int_as_float(c1.y);
        const float v2 = __int_as_float(c2.y);
        const float v3 = __int_as_float(c3.y);
        acc.x = fmaf(v0, q0.x, acc.x); acc.y = fmaf(v0, q0.y, acc.y);
        acc.z = fmaf(v0, q0.z, acc.z); acc.w = fmaf(v0, q0.w, acc.w);
        acc.x = fmaf(v1, q1.x, acc.x); acc.y = fmaf(v1, q1.y, acc.y);
        acc.z = fmaf(v1, q1.z, acc.z); acc.w = fmaf(v1, q1.w, acc.w);
        acc.x = fmaf(v2, q2.x, acc.x); acc.y = fmaf(v2, q2.y, acc.y);
        acc.z = fmaf(v2, q2.z, acc.z); acc.w = fmaf(v2, q2.w, acc.w);
        acc.x = fmaf(v3, q3.x, acc.x); acc.y = fmaf(v3, q3.y, acc.y);
        acc.z = fmaf(v3, q3.z, acc.z); acc.w = fmaf(v3, q3.w, acc.w);
    }

    float4* orow = reinterpret_cast<float4*>(out) + (size_t)row * 16 + lane16;
    float4 o = *orow;
    o.x += acc.x; o.y += acc.y; o.z += acc.z; o.w += acc.w;
    *orow = o;
}

extern "C" void kernel_launch(void* const* d_in, const int* in_sizes, int n_in,
                              void* d_out, int out_size)
{
    const int*   rows = (const int*)  d_in[0];
    const int*   cols = (const int*)  d_in[1];
    const float* vals = (const float*)d_in[2];
    const float* X    = (const float*)d_in[3];
    const float* W1   = (const float*)d_in[4];
    const float* b1   = (const float*)d_in[5];
    const float* W2   = (const float*)d_in[6];
    const float* b2   = (const float*)d_in[7];
    float* out = (float*)d_out;

    const int E = in_sizes[0];
    const int N = in_sizes[3] / FDIM;

    cudaFuncSetAttribute(gnn_dense_hist, cudaFuncAttributeMaxDynamicSharedMemorySize, 49152);

    void* p = nullptr;
    cudaGetSymbolAddress(&p, g_cnt);
    cudaMemsetAsync(p, 0, (size_t)N * sizeof(int));

    const int blocksD = (N + 63) / 64;
    gnn_dense_hist<<<blocksD, 256, 49152>>>(X, W1, b1, W2, b2, rows, out, N, E);

    const int nb = (N + 1023) / 1024;
    scan_blocksums<<<nb, 1024>>>(N);
    scan_bsums<<<1, 128>>>(nb);
    scan_write<<<nb, 1024>>>(N);

    gnn_scatter<<<(E + 255) / 256, 256>>>(rows, cols, vals, E);

    const long long work = (long long)N * 16;
    gnn_spmm_csr<<<(int)((work + 255) / 256), 256>>>(out, N);
}

// round 17
// speedup vs baseline: 1.1109x; 1.0922x over previous
#include <cuda_runtime.h>
#include <cuda_fp16.h>

#define MAX_N 100000
#define MAX_E 1200000
#define MAX_EP (MAX_E + 3 * MAX_N)   // padded bins: each row rounded up to 4
#define FDIM 64

__device__ __half g_Qh[(size_t)MAX_N * FDIM];    // Q = X@W1 + (X*X)@W2, fp16
__device__ int    g_cnt[MAX_N];                  // per-row edge count
__device__ int    g_rank[MAX_E];                 // edge's rank within its row
__device__ int    g_rowstart[MAX_N];             // exclusive scan of padded counts
__device__ int    g_rowend[MAX_N];               // rowstart + cnt
__device__ int2   g_edges[MAX_EP];               // binned (col, val), zero-padded
__device__ int    g_bsum[128];                   // block sums for the scan

// ---- packed f32x2 helpers (sm_103a FFMA2: 2 fp32 FMAs / issue slot) ----
typedef unsigned long long u64;
__device__ __forceinline__ u64 pack2(float lo, float hi) {
    u64 r; asm("mov.b64 %0, {%1, %2};" : "=l"(r) : "f"(lo), "f"(hi)); return r;
}
__device__ __forceinline__ void unpack2(u64 p, float& lo, float& hi) {
    asm("mov.b64 {%0, %1}, %2;" : "=f"(lo), "=f"(hi) : "l"(p));
}
__device__ __forceinline__ u64 fma2(u64 a, u64 b, u64 c) {
    u64 d; asm("fma.rn.f32x2 %0, %1, %2, %3;" : "=l"(d) : "l"(a), "l"(b), "l"(c)); return d;
}
__device__ __forceinline__ u64 mul2(u64 a, u64 b) {
    u64 d; asm("mul.rn.f32x2 %0, %1, %2;" : "=l"(d) : "l"(a), "l"(b)); return d;
}

// ---------------------------------------------------------------------------
// Dense GEMM (f32x2) + fused histogram with rank capture (R16 proven).
// Epilogue now stores Q as fp16 (half the scratch traffic; spmm gathers it).
// ---------------------------------------------------------------------------
__global__ __launch_bounds__(256, 3) void gnn_dense_hist(
    const float* __restrict__ X,
    const float* __restrict__ W1, const float* __restrict__ b1,
    const float* __restrict__ W2, const float* __restrict__ b2,
    const int* __restrict__ rows,
    float* __restrict__ out, int N, int E)
{
    extern __shared__ float smem[];
    float* W1s = smem;          // 64*64 = 16KB
    float* W2s = smem + 4096;   // 16KB
    float* Xs  = smem + 8192;   // 64*64 = 16KB

    const int tid = threadIdx.x;

    #pragma unroll
    for (int i = tid; i < 1024; i += 256) {
        reinterpret_cast<float4*>(W1s)[i] = reinterpret_cast<const float4*>(W1)[i];
        reinterpret_cast<float4*>(W2s)[i] = reinterpret_cast<const float4*>(W2)[i];
    }

    const int row0 = blockIdx.x * 64;
    #pragma unroll
    for (int i = tid; i < 64 * 16; i += 256) {
        const int r  = i >> 4;
        const int gr = row0 + r;
        float4 v = make_float4(0.f, 0.f, 0.f, 0.f);
        if (gr < N) v = reinterpret_cast<const float4*>(X)[(size_t)gr * 16 + (i & 15)];
        reinterpret_cast<float4*>(Xs)[i] = v;
    }

    // Fused histogram + rank capture.
    const int stride = gridDim.x * 256;
    for (int e = blockIdx.x * 256 + tid; e < E; e += stride)
        g_rank[e] = atomicAdd(&g_cnt[__ldg(rows + e)], 1);

    __syncthreads();

    const int rg  = (tid >> 4) * 4;
    const int cg4 = tid & 15;

    const u64* W1p = reinterpret_cast<const u64*>(W1s);
    const u64* W2p = reinterpret_cast<const u64*>(W2s);

    u64 acc1a[4], acc1b[4], acc2a[4], acc2b[4];
    #pragma unroll
    for (int i = 0; i < 4; ++i) { acc1a[i]=0; acc1b[i]=0; acc2a[i]=0; acc2b[i]=0; }

    #pragma unroll 8
    for (int k = 0; k < 64; ++k) {
        const u64 w1a = W1p[k * 32 + 2 * cg4];
        const u64 w1b = W1p[k * 32 + 2 * cg4 + 1];
        const u64 w2a = W2p[k * 32 + 2 * cg4];
        const u64 w2b = W2p[k * 32 + 2 * cg4 + 1];
        #pragma unroll
        for (int i = 0; i < 4; ++i) {
            const float x  = Xs[(rg + i) * 64 + k];
            const u64 xp  = pack2(x, x);
            const u64 xsq = mul2(xp, xp);
            acc1a[i] = fma2(xp,  w1a, acc1a[i]);
            acc1b[i] = fma2(xp,  w1b, acc1b[i]);
            acc2a[i] = fma2(xsq, w2a, acc2a[i]);
            acc2b[i] = fma2(xsq, w2b, acc2b[i]);
        }
    }

    const int cc = cg4 * 4;
    float4 bb;
    bb.x = __ldg(b1 + cc + 0) + __ldg(b2 + cc + 0);
    bb.y = __ldg(b1 + cc + 1) + __ldg(b2 + cc + 1);
    bb.z = __ldg(b1 + cc + 2) + __ldg(b2 + cc + 2);
    bb.w = __ldg(b1 + cc + 3) + __ldg(b2 + cc + 3);

    #pragma unroll
    for (int i = 0; i < 4; ++i) {
        const int gr = row0 + rg + i;
        if (gr < N) {
            float a10, a11, a12, a13, a20, a21, a22, a23;
            unpack2(acc1a[i], a10, a11);
            unpack2(acc1b[i], a12, a13);
            unpack2(acc2a[i], a20, a21);
            unpack2(acc2b[i], a22, a23);
            float4 o;
            o.x = a10 + bb.x;
            o.y = a11 + bb.y;
            o.z = a12 + bb.z;
            o.w = a13 + bb.w;
            reinterpret_cast<float4*>(out)[(size_t)gr * 16 + cg4] = o;
            // Q in fp16: 4 cols -> 2 half2 -> one 8B store
            const __half2 qh0 = __float22half2_rn(
                make_float2(a10 + a20, a11 + a21));
            const __half2 qh1 = __float22half2_rn(
                make_float2(a12 + a22, a13 + a23));
            __half2 qv[2] = {qh0, qh1};
            *reinterpret_cast<uint2*>(g_Qh + (size_t)gr * 64 + cg4 * 4) =
                *reinterpret_cast<uint2*>(qv);
        }
    }
}

// ---------------------------------------------------------------------------
// Scan stage (R16, byte-identical): padded counts vp = (cnt+3)&~3.
// ---------------------------------------------------------------------------
__device__ __forceinline__ int warp_incl_scan(int v) {
    #pragma unroll
    for (int off = 1; off < 32; off <<= 1) {
        int u = __shfl_up_sync(0xffffffffu, v, off);
        if ((threadIdx.x & 31) >= off) v += u;
    }
    return v;
}

__global__ __launch_bounds__(1024) void scan_blocksums(int N) {
    const int i = blockIdx.x * 1024 + threadIdx.x;
    int v = (i < N) ? ((g_cnt[i] + 3) & ~3) : 0;
    #pragma unroll
    for (int off = 16; off > 0; off >>= 1)
        v += __shfl_down_sync(0xffffffffu, v, off);
    __shared__ int ws[32];
    const int lane = threadIdx.x & 31, wid = threadIdx.x >> 5;
    if (lane == 0) ws[wid] = v;
    __syncthreads();
    if (wid == 0) {
        int x = ws[lane];
        #pragma unroll
        for (int off = 16; off > 0; off >>= 1)
            x += __shfl_down_sync(0xffffffffu, x, off);
        if (lane == 0) g_bsum[blockIdx.x] = x;
    }
}

__global__ __launch_bounds__(128) void scan_bsums(int nb) {
    __shared__ int s[128];
    const int t = threadIdx.x;
    s[t] = (t < nb) ? g_bsum[t] : 0;
    __syncthreads();
    #pragma unroll
    for (int off = 1; off < 128; off <<= 1) {
        int v = (t >= off) ? s[t - off] : 0;
        __syncthreads();
        s[t] += v;
        __syncthreads();
    }
    if (t < nb) g_bsum[t] = s[t];
}

__global__ __launch_bounds__(1024) void scan_write(int N) {
    const int t = threadIdx.x, b = blockIdx.x;
    const int i = b * 1024 + t;
    const int cnt = (i < N) ? g_cnt[i] : 0;
    const int vp  = (cnt + 3) & ~3;
    const int lane = t & 31, wid = t >> 5;
    int inc = warp_incl_scan(vp);
    __shared__ int ws[32];
    if (lane == 31) ws[wid] = inc;
    __syncthreads();
    if (wid == 0) {
        int x = ws[lane];
        x = warp_incl_scan(x);
        ws[lane] = x;
    }
    __syncthreads();
    int excl = inc - vp + (wid ? ws[wid - 1] : 0) + (b ? g_bsum[b - 1] : 0);
    if (i < N) {
        g_rowstart[i] = excl;
        g_rowend[i]   = excl + cnt;
        const int2 z = make_int2(0, 0);
        for (int p = excl + cnt; p < excl + vp; ++p) g_edges[p] = z;
    }
}

// ---------------------------------------------------------------------------
// Scatter: atomic-free (R16). pos = rowstart[r] + rank[e].
// ---------------------------------------------------------------------------
__global__ __launch_bounds__(256) void gnn_scatter(
    const int* __restrict__ rows,
    const int* __restrict__ cols,
    const float* __restrict__ vals, int E)
{
    const int e = blockIdx.x * blockDim.x + threadIdx.x;
    if (e >= E) return;
    const int r   = __ldg(rows + e);
    const int pos = __ldg(g_rowstart + r) + __ldg(g_rank + e);
    g_edges[pos] = make_int2(__ldg(cols + e), __float_as_int(__ldg(vals + e)));
}

// ---------------------------------------------------------------------------
// CSR SpMM over fp16 Q: 16 lanes/row, 4 halves (8B) per lane, padded bins,
// edge prefetch. Gather traffic halved vs fp32 Q.
// ---------------------------------------------------------------------------
__device__ __forceinline__ float4 h4tof4(uint2 u) {
    const __half2 h0 = *reinterpret_cast<__half2*>(&u.x);
    const __half2 h1 = *reinterpret_cast<__half2*>(&u.y);
    const float2 f0 = __half22float2(h0);
    const float2 f1 = __half22float2(h1);
    return make_float4(f0.x, f0.y, f1.x, f1.y);
}

__global__ __launch_bounds__(256) void gnn_spmm_csr(float* __restrict__ out, int N)
{
    const int gid = blockIdx.x * blockDim.x + threadIdx.x;
    const int row = gid >> 4;
    if (row >= N) return;
    const int lane16 = gid & 15;

    const int start = __ldg(g_rowstart + row);
    const int end   = __ldg(g_rowend + row);
    const int deg   = end - start;
    if (deg <= 0) return;
    int iters = (deg + 3) >> 2;

    const uint2* __restrict__ Qh = reinterpret_cast<const uint2*>(g_Qh);
    const int2* ep = g_edges + start;

    int2 c0 = __ldg(ep + 0), c1 = __ldg(ep + 1);
    int2 c2 = __ldg(ep + 2), c3 = __ldg(ep + 3);

    float4 acc = make_float4(0.f, 0.f, 0.f, 0.f);

    while (--iters > 0) {
        ep += 4;
        const int2 n0 = __ldg(ep + 0), n1 = __ldg(ep + 1);
        const int2 n2 = __ldg(ep + 2), n3 = __ldg(ep + 3);

        const float4 q0 = h4tof4(__ldg(Qh + (size_t)c0.x * 16 + lane16));
        const float4 q1 = h4tof4(__ldg(Qh + (size_t)c1.x * 16 + lane16));
        const float4 q2 = h4tof4(__ldg(Qh + (size_t)c2.x * 16 + lane16));
        const float4 q3 = h4tof4(__ldg(Qh + (size_t)c3.x * 16 + lane16));
        const float v0 = __int_as_float(c0.y);
        const float v1 = __int_as_float(c1.y);
        const float v2 = __int_as_float(c2.y);
        const float v3 = __int_as_float(c3.y);
        acc.x = fmaf(v0, q0.x, acc.x); acc.y = fmaf(v0, q0.y, acc.y);
        acc.z = fmaf(v0, q0.z, acc.z); acc.w = fmaf(v0, q0.w, acc.w);
        acc.x = fmaf(v1, q1.x, acc.x); acc.y = fmaf(v1, q1.y, acc.y);
        acc.z = fmaf(v1, q1.z, acc.z); acc.w = fmaf(v1, q1.w, acc.w);
        acc.x = fmaf(v2, q2.x, acc.x); acc.y = fmaf(v2, q2.y, acc.y);
        acc.z = fmaf(v2, q2.z, acc.z); acc.w = fmaf(v2, q2.w, acc.w);
        acc.x = fmaf(v3, q3.x, acc.x); acc.y = fmaf(v3, q3.y, acc.y);
        acc.z = fmaf(v3, q3.z, acc.z); acc.w = fmaf(v3, q3.w, acc.w);

        c0 = n0; c1 = n1; c2 = n2; c3 = n3;
    }

    {   // final chunk (padding edges: val=0 -> no-op FMAs)
        const float4 q0 = h4tof4(__ldg(Qh + (size_t)c0.x * 16 + lane16));
        const float4 q1 = h4tof4(__ldg(Qh + (size_t)c1.x * 16 + lane16));
        const float4 q2 = h4tof4(__ldg(Qh + (size_t)c2.x * 16 + lane16));
        const float4 q3 = h4tof4(__ldg(Qh + (size_t)c3.x * 16 + lane16));
        const float v0 = __int_as_float(c0.y);
        const float v1 = __int_as_float(c1.y);
        const float v2 = __int_as_float(c2.y);
        const float v3 = __int_as_float(c3.y);
        acc.x = fmaf(v0, q0.x, acc.x); acc.y = fmaf(v0, q0.y, acc.y);
        acc.z = fmaf(v0, q0.z, acc.z); acc.w = fmaf(v0, q0.w, acc.w);
        acc.x = fmaf(v1, q1.x, acc.x); acc.y = fmaf(v1, q1.y, acc.y);
        acc.z = fmaf(v1, q1.z, acc.z); acc.w = fmaf(v1, q1.w, acc.w);
        acc.x = fmaf(v2, q2.x, acc.x); acc.y = fmaf(v2, q2.y, acc.y);
        acc.z = fmaf(v2, q2.z, acc.z); acc.w = fmaf(v2, q2.w, acc.w);
        acc.x = fmaf(v3, q3.x, acc.x); acc.y = fmaf(v3, q3.y, acc.y);
        acc.z = fmaf(v3, q3.z, acc.z); acc.w = fmaf(v3, q3.w, acc.w);
    }

    float4* orow = reinterpret_cast<float4*>(out) + (size_t)row * 16 + lane16;
    float4 o = *orow;
    o.x += acc.x; o.y += acc.y; o.z += acc.z; o.w += acc.w;
    *orow = o;
}

extern "C" void kernel_launch(void* const* d_in, const int* in_sizes, int n_in,
                              void* d_out, int out_size)
{
    const int*   rows = (const int*)  d_in[0];
    const int*   cols = (const int*)  d_in[1];
    const float* vals = (const float*)d_in[2];
    const float* X    = (const float*)d_in[3];
    const float* W1   = (const float*)d_in[4];
    const float* b1   = (const float*)d_in[5];
    const float* W2   = (const float*)d_in[6];
    const float* b2   = (const float*)d_in[7];
    float* out = (float*)d_out;

    const int E = in_sizes[0];
    const int N = in_sizes[3] / FDIM;

    cudaFuncSetAttribute(gnn_dense_hist, cudaFuncAttributeMaxDynamicSharedMemorySize, 49152);

    void* p = nullptr;
    cudaGetSymbolAddress(&p, g_cnt);
    cudaMemsetAsync(p, 0, (size_t)N * sizeof(int));

    const int blocksD = (N + 63) / 64;
    gnn_dense_hist<<<blocksD, 256, 49152>>>(X, W1, b1, W2, b2, rows, out, N, E);

    const int nb = (N + 1023) / 1024;
    scan_blocksums<<<nb, 1024>>>(N);
    scan_bsums<<<1, 128>>>(nb);
    scan_write<<<nb, 1024>>>(N);

    gnn_scatter<<<(E + 255) / 256, 256>>>(rows, cols, vals, E);

    const long long work = (long long)N * 16;
    gnn_spmm_csr<<<(int)((work + 255) / 256), 256>>>(out, N);
}